// round 16
// baseline (speedup 1.0000x reference)
#include <cuda_runtime.h>
#include <cuda_fp16.h>
#include <cstdint>
#include <math.h>

// Problem constants
#define BATCH 2
#define C 256
#define H 64
#define W 64
#define HW 4096
#define K2 9
#define CO 256
#define CK 2304        // C*K2

// Scratch (__device__ globals; allocation-free rule; zero-initialized)
__device__ float  g_part[BATCH * 27 * HW];         // conv outputs [b][27][p]
__device__ __align__(16) __half g_vh[(size_t)BATCH * CK * HW];   // [b][ck][p]
__device__ __align__(16) __half g_wh[(size_t)CO * CK];           // W fp16
__device__ __align__(16) __half g_xt[(size_t)BATCH * HW * C];    // [b][p][c] fp16
__device__ __align__(16) __half g_cw[2 * 2 * 32 * CK];           // conv W planes
__device__ float  g_po[(size_t)BATCH * CO * HW];   // split-K partial output

// ---------------------------------------------------------------------------
// helpers
// ---------------------------------------------------------------------------
__device__ __forceinline__ uint32_t smem_u32(const void* p) {
    uint32_t a;
    asm("{ .reg .u64 t; cvta.to.shared.u64 t, %1; cvt.u32.u64 %0, t; }" : "=r"(a) : "l"(p));
    return a;
}
__device__ __forceinline__ void cp_async16(uint32_t dst, const void* src) {
    asm volatile("cp.async.cg.shared.global [%0], [%1], 16;" :: "r"(dst), "l"(src));
}
#define CP_COMMIT() asm volatile("cp.async.commit_group;" ::: "memory")
#define CP_WAIT(n)  asm volatile("cp.async.wait_group %0;" :: "n"(n) : "memory")
#define SWZ128(off) ((off) ^ (((off) >> 3) & 0x70))

#define LDSM4(r, addr) \
    asm volatile("ldmatrix.sync.aligned.m8n8.x4.shared.b16 {%0,%1,%2,%3}, [%4];" \
        : "=r"((r)[0]), "=r"((r)[1]), "=r"((r)[2]), "=r"((r)[3]) : "r"(addr))
#define LDSM4T(r, addr) \
    asm volatile("ldmatrix.sync.aligned.m8n8.x4.trans.shared.b16 {%0,%1,%2,%3}, [%4];" \
        : "=r"((r)[0]), "=r"((r)[1]), "=r"((r)[2]), "=r"((r)[3]) : "r"(addr))

__device__ __forceinline__ void mma16816(float c[4], const uint32_t a[4], const uint32_t b[2]) {
    asm volatile(
        "mma.sync.aligned.m16n8k16.row.col.f32.f16.f16.f32 "
        "{%0,%1,%2,%3}, {%4,%5,%6,%7}, {%8,%9}, {%0,%1,%2,%3};"
        : "+f"(c[0]), "+f"(c[1]), "+f"(c[2]), "+f"(c[3])
        : "r"(a[0]), "r"(a[1]), "r"(a[2]), "r"(a[3]), "r"(b[0]), "r"(b[1]));
}

__device__ __forceinline__ void h8f(const uint4 v, float* f) {
    const __half2* h = (const __half2*)&v;
#pragma unroll
    for (int j = 0; j < 4; ++j) {
        const float2 t = __half22float2(h[j]);
        f[2 * j] = t.x; f[2 * j + 1] = t.y;
    }
}

// ---------------------------------------------------------------------------
// Kernel 1 (prep): blocks 0..143 W->fp16; 144..1167 transpose x -> g_xt;
// 1168..1199 conv weights -> hi/lo fp16 planes g_cw.
// ---------------------------------------------------------------------------
__global__ __launch_bounds__(128)
void prep_kernel(const float* __restrict__ x,
                 const float* __restrict__ ow,   // [18][C][9]
                 const float* __restrict__ mw,   // [9][C][9]
                 const float* __restrict__ rw)   // [256][C][9]
{
    __shared__ __align__(16) float sw[64 * 33];

    const int tid  = threadIdx.x;
    const int bidx = blockIdx.x;

    if (bidx < 144) {
        const int n4 = CO * CK / 4;                // 147456 float4
        for (int i = bidx * 128 + tid; i < n4; i += 144 * 128) {
            const float4 v = ((const float4*)rw)[i];
            __half2* dst = (__half2*)(g_wh + (size_t)i * 4);
            dst[0] = __floats2half2_rn(v.x, v.y);
            dst[1] = __floats2half2_rn(v.z, v.w);
        }
        return;
    }

    if (bidx < 1168) {
        // transpose: tile 64 c x 32 p
        const int t  = bidx - 144;                 // 0..1023
        const int p0 = (t & 127) * 32;
        const int c0 = ((t >> 7) & 3) * 64;
        const int b  = t >> 9;
        float (*s32)[33] = (float(*)[33])sw;
        const int lane = tid & 31;
        const int wi   = tid >> 5;
        const float* xb = x + ((size_t)(b * C + c0)) * HW + p0;
#pragma unroll
        for (int i = 0; i < 16; ++i) {
            const int cl = wi * 16 + i;
            s32[cl][lane] = xb[(size_t)cl * HW + lane];
        }
        __syncthreads();
        __half2* dst = (__half2*)(g_xt + ((size_t)(b * HW + p0)) * C + c0);
#pragma unroll
        for (int i = 0; i < 8; ++i) {
            const int pl = wi * 8 + i;
            dst[(size_t)pl * (C / 2) + lane] =
                __floats2half2_rn(s32[lane * 2][pl], s32[lane * 2 + 1][pl]);
        }
        return;
    }

    // conv weights -> g_cw[e][pl][row][ck]; rows beyond M_e stay zero (.bss)
    const int n = 27 * CK;                         // 62208
    for (int i = (bidx - 1168) * 128 + tid; i < n; i += 32 * 128) {
        const int o  = i / CK;
        const int ck = i - o * CK;
        const float v = (o < 18) ? ow[(size_t)o * CK + ck]
                                 : mw[(size_t)(o - 18) * CK + ck];
        const __half hi = __float2half_rn(v);
        const __half lo = __float2half_rn(v - __half2float(hi));
        const int e   = (o < 18) ? 0 : 1;
        const int row = (o < 18) ? o : o - 18;
        g_cw[((size_t)(e * 2 + 0) * 32 + row) * CK + ck] = hi;
        g_cw[((size_t)(e * 2 + 1) * 32 + row) * CK + ck] = lo;
    }
}

// ---------------------------------------------------------------------------
// Kernel 2: implicit-GEMM conv, split-fp16 (hi/lo) tensor cores.
// Grid (64 rows, BATCH*2). Tile M=32 x N=64 x K=2304 (36 chunks of 64).
// smem: A hi [0,4K) | A lo [4K,8K) | B hi [8K,24K) | B lo [24K,40K).
// B rows padded to 256B; store/frag swizzle copied verbatim from the
// long-proven main-GEMM B path (cols 0..7 used, 8..15 never read).
// ---------------------------------------------------------------------------
#define CONV_SMEM 40960
__global__ __launch_bounds__(256)
void conv_gemm_kernel(const float* __restrict__ res,
                      const float* __restrict__ x)
{
    extern __shared__ char cs[];
    const uint32_t sb = smem_u32(cs);

    const int tid  = threadIdx.x;
    const int lane = tid & 31;
    const int wid  = tid >> 5;
    const int h0   = blockIdx.x;                 // image row 0..63
    const int b    = blockIdx.y >> 1;
    const int e    = blockIdx.y & 1;             // 0: offsets(res), 1: mod(x)

    const float* src = (e ? x : res) + (size_t)b * C * HW;

    // ---- A construct: 2 planes x 32 rows x 64 halves (SW128, 128B rows) ----
    const int apl = tid >> 7;
    const int ar  = (tid & 127) >> 2;
    const int as  = (tid & 3) * 16;              // half offset within row
    const __half* agsrc = g_cw + ((size_t)((e * 2 + apl) * 32 + ar)) * CK + as;
    const uint32_t asmo0 = (uint32_t)apl * 4096 + SWZ128((uint32_t)(ar * 128 + as * 2));
    const uint32_t asmo1 = (uint32_t)apl * 4096 + SWZ128((uint32_t)(ar * 128 + as * 2 + 16));

    // ---- B construct: 64 rows x 256B; thread = (row=tid>>2, colpair=tid&3) ----
    const int brow = tid >> 2;
    const int cgp  = tid & 3;
    const int be0  = cgp * 16;                   // element base (halves)
    const uint32_t bst0 = (uint32_t)brow * 256 + ((uint32_t)((cgp * 2)     ^ (brow & 7)) << 4);
    const uint32_t bst1 = (uint32_t)brow * 256 + ((uint32_t)((cgp * 2 + 1) ^ (brow & 7)) << 4);

    // ---- fragment offsets ----
    const int wm = (wid >> 2) * 16;              // 0 / 16
    const int n0 = (wid & 3) * 16;               // 0..48
    const uint32_t aOff = SWZ128((uint32_t)((wm + (lane & 15)) * 128
                                            + ((lane & 16) ? 16 : 0)));
    const int mIdx = lane >> 3;
    const int koff = ((mIdx & 1) << 3) + (lane & 7);
    const int cc0  = (n0 >> 3) + (mIdx >> 1);
    const uint32_t bO = (uint32_t)koff * 256 + ((uint32_t)(cc0 ^ (koff & 7)) << 4);

    float acc[2][4];
#pragma unroll
    for (int i = 0; i < 2; ++i)
#pragma unroll
        for (int j = 0; j < 4; ++j) acc[i][j] = 0.f;

    for (int ch = 0; ch < 36; ++ch) {
        // A tile (16 halves/thread from g_cw)
        {
            const __half* gs = agsrc + ch * 64;
            const uint4 v0 = *(const uint4*)gs;
            const uint4 v1 = *(const uint4*)(gs + 8);
            *(uint4*)(cs + asmo0) = v0;
            *(uint4*)(cs + asmo1) = v1;
        }
        // B tile: 16 predicated source floats -> hi/lo halves
        {
            const int ck = ch * 64 + brow;
            const int c  = ck / 9;
            const int k  = ck - 9 * c;
            const int dy = k / 3 - 1;
            const int dx = k - (k / 3) * 3 - 1;
            const int hh = h0 + dy;
            const bool vh = ((unsigned)hh < 64u);

            uint32_t hw_[8], lw_[8];
#pragma unroll
            for (int jj = 0; jj < 8; ++jj) {
                float f0 = 0.f, f1 = 0.f;
                const int w0 = be0 + 2 * jj + dx;
                const int w1 = w0 + 1;
                if (vh && (unsigned)w0 < 64u)
                    f0 = __ldg(src + (size_t)c * HW + (size_t)(hh * 64 + w0));
                if (vh && (unsigned)w1 < 64u)
                    f1 = __ldg(src + (size_t)c * HW + (size_t)(hh * 64 + w1));
                const __half h0h = __float2half_rn(f0);
                const __half h1h = __float2half_rn(f1);
                const __half l0h = __float2half_rn(f0 - __half2float(h0h));
                const __half l1h = __float2half_rn(f1 - __half2float(h1h));
                hw_[jj] = (uint32_t)__half_as_ushort(h0h) | ((uint32_t)__half_as_ushort(h1h) << 16);
                lw_[jj] = (uint32_t)__half_as_ushort(l0h) | ((uint32_t)__half_as_ushort(l1h) << 16);
            }
            uint4 v;
            v.x = hw_[0]; v.y = hw_[1]; v.z = hw_[2]; v.w = hw_[3];
            *(uint4*)(cs + 8192 + bst0) = v;
            v.x = hw_[4]; v.y = hw_[5]; v.z = hw_[6]; v.w = hw_[7];
            *(uint4*)(cs + 8192 + bst1) = v;
            v.x = lw_[0]; v.y = lw_[1]; v.z = lw_[2]; v.w = lw_[3];
            *(uint4*)(cs + 24576 + bst0) = v;
            v.x = lw_[4]; v.y = lw_[5]; v.z = lw_[6]; v.w = lw_[7];
            *(uint4*)(cs + 24576 + bst1) = v;
        }
        __syncthreads();

#pragma unroll
        for (int s = 0; s < 4; ++s) {
            uint32_t ah[4], al[4], bh[4], bl[4];
            LDSM4(ah, sb + (aOff ^ (s << 5)));
            LDSM4(al, sb + 4096 + (aOff ^ (s << 5)));
            LDSM4T(bh, sb + 8192  + bO + s * 4096);
            LDSM4T(bl, sb + 24576 + bO + s * 4096);
#pragma unroll
            for (int nf = 0; nf < 2; ++nf) {
                mma16816(acc[nf], ah, &bh[2 * nf]);
                mma16816(acc[nf], ah, &bl[2 * nf]);
                mma16816(acc[nf], al, &bh[2 * nf]);
            }
        }
        __syncthreads();
    }

    // epilogue
    const int qr = lane >> 2;
    const int qc = lane & 3;
    const int Me    = e ? 9 : 18;
    const int obase = e ? 18 : 0;
    float* gp = g_part + (size_t)b * 27 * HW;
#pragma unroll
    for (int nf = 0; nf < 2; ++nf) {
        const int p = h0 * 64 + n0 + nf * 8 + 2 * qc;
        const int m = wm + qr;
        if (m < Me) {
            float2 v; v.x = acc[nf][0]; v.y = acc[nf][1];
            *(float2*)(gp + (size_t)(obase + m) * HW + p) = v;
        }
        if (m + 8 < Me) {
            float2 v; v.x = acc[nf][2]; v.y = acc[nf][3];
            *(float2*)(gp + (size_t)(obase + m + 8) * HW + p) = v;
        }
    }
}

// ---------------------------------------------------------------------------
// Kernel 3: sampling v3 (R12) — direct conv-output reads.
// ---------------------------------------------------------------------------
#define SVROW 37
#define SAMPLE_DSMEM (288 * SVROW * 4)   // 42624 B
__global__ __launch_bounds__(256)
void sample_kernel(const float* __restrict__ ob,   // [18]
                   const float* __restrict__ mb)   // [9]
{
    __shared__ int   sl0[288], sl1[288], sl2[288], sl3[288];
    __shared__ float sw0[288], sw1[288], sw2[288], sw3[288];
    extern __shared__ uint32_t sv[];

    const int tid  = threadIdx.x;
    const int lane = tid & 31;
    const int wid  = tid >> 5;
    const int b    = blockIdx.y;
    const int p0   = blockIdx.x * 32;

    const float* gp = g_part + (size_t)b * 27 * HW;
    for (int pk = tid; pk < 288; pk += 256) {
        const int px = pk / 9;
        const int k  = pk - px * 9;
        const int p  = p0 + px;
        const int h  = p >> 6;
        const int w  = p & 63;

        const float dy   = ob[2 * k]     + gp[(size_t)(2 * k) * HW + p];
        const float dx   = ob[2 * k + 1] + gp[(size_t)(2 * k + 1) * HW + p];
        const float mraw = mb[k]         + gp[(size_t)(18 + k) * HW + p];
        const float m = 2.f / (1.f + expf(-mraw));

        const float py  = dy + (float)(h - 1 + k / 3);
        const float px_ = dx + (float)(w - 1 + k % 3);
        const float y0f = floorf(py), x0f = floorf(px_);
        const float wy1 = py - y0f,  wx1 = px_ - x0f;
        const float wy0 = 1.f - wy1, wx0 = 1.f - wx1;
        const int y0 = (int)y0f, x0 = (int)x0f;
        const int y1 = y0 + 1,   x1 = x0 + 1;

        bool v; int yc, xc;
        v = ((unsigned)y0 < 64u) && ((unsigned)x0 < 64u);
        yc = min(max(y0, 0), 63); xc = min(max(x0, 0), 63);
        sl0[pk] = yc * 64 + xc; sw0[pk] = v ? wy0 * wx0 * m : 0.f;
        v = ((unsigned)y0 < 64u) && ((unsigned)x1 < 64u);
        yc = min(max(y0, 0), 63); xc = min(max(x1, 0), 63);
        sl1[pk] = yc * 64 + xc; sw1[pk] = v ? wy0 * wx1 * m : 0.f;
        v = ((unsigned)y1 < 64u) && ((unsigned)x0 < 64u);
        yc = min(max(y1, 0), 63); xc = min(max(x0, 0), 63);
        sl2[pk] = yc * 64 + xc; sw2[pk] = v ? wy1 * wx0 * m : 0.f;
        v = ((unsigned)y1 < 64u) && ((unsigned)x1 < 64u);
        yc = min(max(y1, 0), 63); xc = min(max(x1, 0), 63);
        sl3[pk] = yc * 64 + xc; sw3[pk] = v ? wy1 * wx1 * m : 0.f;
    }
    __syncthreads();

    const __half* xtb = g_xt + (size_t)b * HW * C;
    const int grp = lane >> 3;
    const int lg  = lane & 7;

    for (int c0 = 0; c0 < C; c0 += 64) {
#pragma unroll
        for (int i = 0; i < 9; ++i) {
            const int pk = wid * 36 + i * 4 + grp;
            const int c  = c0 + lg * 8;
            const float w0 = sw0[pk], w1 = sw1[pk], w2 = sw2[pk], w3 = sw3[pk];
            const uint4 v0 = *(const uint4*)(xtb + (size_t)sl0[pk] * C + c);
            const uint4 v1 = *(const uint4*)(xtb + (size_t)sl1[pk] * C + c);
            const uint4 v2 = *(const uint4*)(xtb + (size_t)sl2[pk] * C + c);
            const uint4 v3 = *(const uint4*)(xtb + (size_t)sl3[pk] * C + c);
            float a[8], bb[8], cc[8], dd[8];
            h8f(v0, a); h8f(v1, bb); h8f(v2, cc); h8f(v3, dd);
            uint32_t o[4];
            __half2* oh = (__half2*)o;
#pragma unroll
            for (int j = 0; j < 4; ++j) {
                const float f0 = w0 * a[2*j]   + w1 * bb[2*j]   + w2 * cc[2*j]   + w3 * dd[2*j];
                const float f1 = w0 * a[2*j+1] + w1 * bb[2*j+1] + w2 * cc[2*j+1] + w3 * dd[2*j+1];
                oh[j] = __floats2half2_rn(f0, f1);
            }
            uint32_t* srow = sv + pk * SVROW + lg * 4;
            srow[0] = o[0]; srow[1] = o[1]; srow[2] = o[2]; srow[3] = o[3];
        }
        __syncthreads();

        const __half* svh = (const __half*)sv;
        for (int t = 0; t < 72; ++t) {
            const int r  = wid * 72 + t;
            const int k  = r >> 6;
            const int cl = r & 63;
            const __half val = svh[(size_t)(lane * 9 + k) * (SVROW * 2) + cl];
            g_vh[((size_t)b * CK + (size_t)(c0 + cl) * 9 + k) * HW + p0 + lane] = val;
        }
        __syncthreads();
    }
}

// ---------------------------------------------------------------------------
// Kernel 4: fp16 mma.sync GEMM, split-K by 2 (R12 version, unchanged).
// ---------------------------------------------------------------------------
#define BKH    64
#define ATILEB 16384
#define BTILEB 16384
#define STAGEB (ATILEB + BTILEB)
#define NSTAGE 3
#define NCHH   18
#define GEMM_SMEM (NSTAGE * STAGEB)      // 98304 B

__global__ __launch_bounds__(256, 2)
void gemm_mma_kernel(float* __restrict__ out)
{
    extern __shared__ char smc[];
    const uint32_t sb = smem_u32(smc);

    const int tid  = threadIdx.x;
    const int lane = tid & 31;
    const int wid  = tid >> 5;
    const int bz   = blockIdx.z;
    const int b    = bz >> 1;
    const int kh   = bz & 1;
    const int m0   = blockIdx.y * 128;
    const int n0   = blockIdx.x * 128;

    const __half* gA = g_wh + (size_t)m0 * CK + (size_t)kh * NCHH * BKH;
    const __half* gB = g_vh + (size_t)b * CK * HW + (size_t)kh * NCHH * BKH * HW + n0;

    const int ar  = tid >> 1;
    const int seg = tid & 1;
    const __half* pa = gA + (size_t)ar * CK + seg * 32;
    uint32_t aswo[4];
#pragma unroll
    for (int j = 0; j < 4; ++j)
        aswo[j] = SWZ128((uint32_t)(ar * 128 + seg * 64 + j * 16));

    const int br = tid >> 2;
    const int cg = tid & 3;
    const __half* pv = gB + (size_t)br * HW + cg * 32;
    uint32_t bswo[4];
#pragma unroll
    for (int j = 0; j < 4; ++j) {
        const int cc = cg * 4 + j;
        bswo[j] = ATILEB + (uint32_t)br * 256 + ((uint32_t)(cc ^ (br & 7)) << 4);
    }

#define LOAD_TILE(stage, ch) do {                                             \
        const uint32_t _s = sb + (stage) * STAGEB;                            \
        const __half* _pa = pa + (size_t)(ch) * BKH;                          \
        cp_async16(_s + aswo[0], _pa);                                        \
        cp_async16(_s + aswo[1], _pa + 8);                                    \
        cp_async16(_s + aswo[2], _pa + 16);                                   \
        cp_async16(_s + aswo[3], _pa + 24);                                   \
        const __half* _pv = pv + (size_t)(ch) * BKH * HW;                     \
        cp_async16(_s + bswo[0], _pv);                                        \
        cp_async16(_s + bswo[1], _pv + 8);                                    \
        cp_async16(_s + bswo[2], _pv + 16);                                   \
        cp_async16(_s + bswo[3], _pv + 24);                                   \
    } while (0)

    const int wm = (wid >> 2) * 64;
    const int wn = (wid & 3) * 32;
    uint32_t aOff[4];
#pragma unroll
    for (int mt = 0; mt < 4; ++mt) {
        const uint32_t off = (uint32_t)((wm + mt * 16 + (lane & 15)) * 128
                                        + ((lane & 16) ? 16 : 0));
        aOff[mt] = SWZ128(off);
    }
    const int mIdx = lane >> 3;
    const int koff = ((mIdx & 1) << 3) + (lane & 7);
    const int cc0  = (wn >> 3) + (mIdx >> 1);
    const int cc1  = cc0 + 2;
    const uint32_t bO0 = ATILEB + (uint32_t)koff * 256 + ((uint32_t)(cc0 ^ (koff & 7)) << 4);
    const uint32_t bO1 = ATILEB + (uint32_t)koff * 256 + ((uint32_t)(cc1 ^ (koff & 7)) << 4);

    float c[16][4];
#pragma unroll
    for (int i = 0; i < 16; ++i)
#pragma unroll
        for (int j = 0; j < 4; ++j) c[i][j] = 0.f;

    LOAD_TILE(0, 0); CP_COMMIT();
    LOAD_TILE(1, 1); CP_COMMIT();

    int stage = 0;
    for (int ch = 0; ch < NCHH; ++ch) {
        if (ch + 2 < NCHH) {
            const int ns = (stage + 2 >= NSTAGE) ? stage + 2 - NSTAGE : stage + 2;
            LOAD_TILE(ns, ch + 2);
        }
        CP_COMMIT();
        CP_WAIT(2);
        __syncthreads();

        const uint32_t sbase = sb + stage * STAGEB;
#pragma unroll
        for (int s = 0; s < 4; ++s) {
            uint32_t a[4][4], b0[4], b1[4];
#pragma unroll
            for (int mt = 0; mt < 4; ++mt)
                LDSM4(a[mt], sbase + (aOff[mt] ^ (s << 5)));
            LDSM4T(b0, sbase + bO0 + s * 4096);
            LDSM4T(b1, sbase + bO1 + s * 4096);
#pragma unroll
            for (int mt = 0; mt < 4; ++mt) {
                mma16816(c[mt * 4 + 0], a[mt], &b0[0]);
                mma16816(c[mt * 4 + 1], a[mt], &b0[2]);
                mma16816(c[mt * 4 + 2], a[mt], &b1[0]);
                mma16816(c[mt * 4 + 3], a[mt], &b1[2]);
            }
        }
        __syncthreads();
        stage = (stage + 1 >= NSTAGE) ? 0 : stage + 1;
    }

    float* dstb = (kh == 0) ? out : g_po;
    const int qr = lane >> 2;
    const int qc = lane & 3;
#pragma unroll
    for (int mt = 0; mt < 4; ++mt) {
#pragma unroll
        for (int nt = 0; nt < 4; ++nt) {
            const int o = m0 + wm + mt * 16 + qr;
            const int p = n0 + wn + nt * 8 + 2 * qc;
            float* o0 = dstb + ((size_t)(b * CO + o)) * HW + p;
            float2 v0; v0.x = c[mt * 4 + nt][0]; v0.y = c[mt * 4 + nt][1];
            *(float2*)o0 = v0;
            float2 v1; v1.x = c[mt * 4 + nt][2]; v1.y = c[mt * 4 + nt][3];
            *(float2*)(o0 + 8 * HW) = v1;
        }
    }
}

// ---------------------------------------------------------------------------
// Kernel 5: split-K reduce  out += g_po
// ---------------------------------------------------------------------------
__global__ __launch_bounds__(256)
void reduce_kernel(float* __restrict__ out)
{
    const int i = blockIdx.x * 256 + threadIdx.x;
    float4 a = ((float4*)out)[i];
    const float4 p = ((const float4*)g_po)[i];
    a.x += p.x; a.y += p.y; a.z += p.z; a.w += p.w;
    ((float4*)out)[i] = a;
}

// ---------------------------------------------------------------------------
extern "C" void kernel_launch(void* const* d_in, const int* in_sizes, int n_in,
                              void* d_out, int out_size)
{
    const float* x   = (const float*)d_in[0];
    const float* res = (const float*)d_in[1];
    const float* ow  = (const float*)d_in[2];
    const float* ob  = (const float*)d_in[3];
    const float* mw  = (const float*)d_in[4];
    const float* mb  = (const float*)d_in[5];
    const float* rw  = (const float*)d_in[6];
    float* out = (float*)d_out;

    static int smem_set = 0;
    if (!smem_set) {
        cudaFuncSetAttribute(gemm_mma_kernel,
                             cudaFuncAttributeMaxDynamicSharedMemorySize, GEMM_SMEM);
        cudaFuncSetAttribute(sample_kernel,
                             cudaFuncAttributeMaxDynamicSharedMemorySize, SAMPLE_DSMEM);
        smem_set = 1;
    }

    prep_kernel<<<1200, 128>>>(x, ow, mw, rw);
    conv_gemm_kernel<<<dim3(64, BATCH * 2), 256, CONV_SMEM>>>(res, x);
    sample_kernel<<<dim3(HW / 32, BATCH), 256, SAMPLE_DSMEM>>>(ob, mb);
    gemm_mma_kernel<<<dim3(HW / 128, CO / 128, BATCH * 2), 256, GEMM_SMEM>>>(out);
    reduce_kernel<<<BATCH * CO * HW / 4 / 256, 256>>>(out);
}

// round 17
// speedup vs baseline: 1.2976x; 1.2976x over previous
#include <cuda_runtime.h>
#include <cuda_fp16.h>
#include <cstdint>
#include <math.h>

// Problem constants
#define BATCH 2
#define C 256
#define H 64
#define W 64
#define HW 4096
#define K2 9
#define CO 256
#define CK 2304        // C*K2
#define G 32           // channel groups for conv partial sums (8 ch each)

// Scratch (__device__ globals; allocation-free rule)
__device__ float  g_part[BATCH * G * 27 * HW];     // [b][g][o(27)][p]
__device__ __half g_vh[(size_t)BATCH * CK * HW];   // [b][ck][p]  p-contiguous fp16
__device__ __half g_wh[(size_t)CO * CK];           // W fp16, K-major rows of o
__device__ __half g_xt[(size_t)BATCH * HW * C];    // x transposed: [b][p][c] fp16
__device__ float  g_po[(size_t)BATCH * CO * HW];   // split-K partial output

// ---------------------------------------------------------------------------
// helpers
// ---------------------------------------------------------------------------
__device__ __forceinline__ uint32_t smem_u32(const void* p) {
    uint32_t a;
    asm("{ .reg .u64 t; cvta.to.shared.u64 t, %1; cvt.u32.u64 %0, t; }" : "=r"(a) : "l"(p));
    return a;
}
__device__ __forceinline__ void cp_async16(uint32_t dst, const void* src) {
    asm volatile("cp.async.cg.shared.global [%0], [%1], 16;" :: "r"(dst), "l"(src));
}
#define CP_COMMIT() asm volatile("cp.async.commit_group;" ::: "memory")
#define CP_WAIT(n)  asm volatile("cp.async.wait_group %0;" :: "n"(n) : "memory")
#define SWZ128(off) ((off) ^ (((off) >> 3) & 0x70))

#define LDSM4(r, addr) \
    asm volatile("ldmatrix.sync.aligned.m8n8.x4.shared.b16 {%0,%1,%2,%3}, [%4];" \
        : "=r"((r)[0]), "=r"((r)[1]), "=r"((r)[2]), "=r"((r)[3]) : "r"(addr))
#define LDSM4T(r, addr) \
    asm volatile("ldmatrix.sync.aligned.m8n8.x4.trans.shared.b16 {%0,%1,%2,%3}, [%4];" \
        : "=r"((r)[0]), "=r"((r)[1]), "=r"((r)[2]), "=r"((r)[3]) : "r"(addr))

__device__ __forceinline__ void mma16816(float c[4], const uint32_t a[4], const uint32_t b[2]) {
    asm volatile(
        "mma.sync.aligned.m16n8k16.row.col.f32.f16.f16.f32 "
        "{%0,%1,%2,%3}, {%4,%5,%6,%7}, {%8,%9}, {%0,%1,%2,%3};"
        : "+f"(c[0]), "+f"(c[1]), "+f"(c[2]), "+f"(c[3])
        : "r"(a[0]), "r"(a[1]), "r"(a[2]), "r"(a[3]), "r"(b[0]), "r"(b[1]));
}

__device__ __forceinline__ void h8f(const uint4 v, float* f) {
    const __half2* h = (const __half2*)&v;
#pragma unroll
    for (int j = 0; j < 4; ++j) {
        const float2 t = __half22float2(h[j]);
        f[2 * j] = t.x; f[2 * j + 1] = t.y;
    }
}

// ---------------------------------------------------------------------------
// Kernel 1: blocks 0..511 conv (8 ch/group, 4 px/thread, 2 passes);
// blocks 512..655 W->fp16; blocks 656..1679 transpose x -> g_xt[b][p][c].
// ---------------------------------------------------------------------------
__global__ __launch_bounds__(128)
void conv_offmod_kernel(const float* __restrict__ x,
                        const float* __restrict__ res,
                        const float* __restrict__ ow,   // [18][C][9]
                        const float* __restrict__ mw,   // [9][C][9]
                        const float* __restrict__ rw)   // [256][C][9]
{
    __shared__ __align__(16) float sw[2592];             // 8*27*12 >= 64*33

    const int tid  = threadIdx.x;
    const int bidx = blockIdx.x;

    if (bidx >= 656) {
        // transpose: tile 64 c x 32 p
        const int t  = bidx - 656;                 // 0..1023
        const int p0 = (t & 127) * 32;
        const int c0 = ((t >> 7) & 3) * 64;
        const int b  = t >> 9;
        float (*s32)[33] = (float(*)[33])sw;
        const int lane = tid & 31;
        const int wi   = tid >> 5;                 // 0..3
        const float* xb = x + ((size_t)(b * C + c0)) * HW + p0;
#pragma unroll
        for (int i = 0; i < 16; ++i) {
            const int cl = wi * 16 + i;
            s32[cl][lane] = xb[(size_t)cl * HW + lane];
        }
        __syncthreads();
        __half2* dst = (__half2*)(g_xt + ((size_t)(b * HW + p0)) * C + c0);
#pragma unroll
        for (int i = 0; i < 8; ++i) {
            const int pl = wi * 8 + i;
            dst[(size_t)pl * (C / 2) + lane] =
                __floats2half2_rn(s32[lane * 2][pl], s32[lane * 2 + 1][pl]);
        }
        return;
    }

    if (bidx >= 512) {
        // fused prep_w: convert reg_w to fp16
        const int n4 = CO * CK / 4;                // 147456 float4
        for (int i = (bidx - 512) * 128 + tid; i < n4; i += 144 * 128) {
            const float4 v = ((const float4*)rw)[i];
            __half2* dst = (__half2*)(g_wh + (size_t)i * 4);
            dst[0] = __floats2half2_rn(v.x, v.y);
            dst[1] = __floats2half2_rn(v.z, v.w);
        }
        return;
    }

    // ---- conv: 512 blocks = B(2) x G(32) x 8 pixel-blocks, 4 px/thread ----
    const int pblk = bidx & 7;
    const int g    = (bidx >> 3) & (G - 1);
    const int b    = bidx >> 8;
    const int p    = pblk * 512 + tid * 4;
    const int h    = p >> 6;
    const int w    = p & 63;

    const int cbase = g * 8;
    // stage weights for this group's 8 channels (all 27 outputs, pad 12)
    for (int i = tid; i < 8 * 243; i += 128) {
        const int ci = i / 243;
        const int t  = i % 243;
        const int c  = cbase + ci;
        const int o  = t / 9;
        const int tt = t % 9;
        float wv;
        if (o < 18) wv = ow[(size_t)o * CK + c * 9 + tt];
        else        wv = mw[(size_t)(o - 18) * CK + c * 9 + tt];
        sw[ci * 324 + o * 12 + tt] = wv;
    }
    __syncthreads();

    float* outp = g_part + (size_t)(b * G + g) * 27 * HW;

    // Pass A: 18 offset outputs from residual
    {
        float acc[18][4];
#pragma unroll
        for (int o = 0; o < 18; ++o)
#pragma unroll
            for (int j = 0; j < 4; ++j) acc[o][j] = 0.f;

        const float* rb = res + (size_t)b * C * HW;
        for (int ci = 0; ci < 8; ++ci) {
            const float* rc = rb + (size_t)(cbase + ci) * HW;
            float rv[18];   // 3 rows x 6 cols
#pragma unroll
            for (int r = 0; r < 3; ++r) {
                const int hh = h + r - 1;
                const bool vy = ((unsigned)hh < 64u);
#pragma unroll
                for (int s = 0; s < 6; ++s) {
                    const int ww = w + s - 1;
                    const bool v = vy && ((unsigned)ww < 64u);
                    rv[r * 6 + s] = v ? rc[hh * 64 + ww] : 0.f;
                }
            }
            const float* swc = sw + ci * 324;
#pragma unroll
            for (int o = 0; o < 18; ++o) {
                const float4 wA = *(const float4*)(swc + o * 12);
                const float4 wB = *(const float4*)(swc + o * 12 + 4);
                const float  w8 = swc[o * 12 + 8];
#pragma unroll
                for (int j = 0; j < 4; ++j) {
                    acc[o][j] += wA.x * rv[j]      + wA.y * rv[j + 1]  + wA.z * rv[j + 2]
                               + wA.w * rv[j + 6]  + wB.x * rv[j + 7]  + wB.y * rv[j + 8]
                               + wB.z * rv[j + 12] + wB.w * rv[j + 13] + w8  * rv[j + 14];
                }
            }
        }
#pragma unroll
        for (int o = 0; o < 18; ++o) {
            float4 v; v.x = acc[o][0]; v.y = acc[o][1]; v.z = acc[o][2]; v.w = acc[o][3];
            *(float4*)(outp + o * HW + p) = v;
        }
    }

    // Pass B: 9 modulator outputs from x
    {
        float acc[9][4];
#pragma unroll
        for (int o = 0; o < 9; ++o)
#pragma unroll
            for (int j = 0; j < 4; ++j) acc[o][j] = 0.f;

        const float* xb = x + (size_t)b * C * HW;
        for (int ci = 0; ci < 8; ++ci) {
            const float* xc = xb + (size_t)(cbase + ci) * HW;
            float xv[18];
#pragma unroll
            for (int r = 0; r < 3; ++r) {
                const int hh = h + r - 1;
                const bool vy = ((unsigned)hh < 64u);
#pragma unroll
                for (int s = 0; s < 6; ++s) {
                    const int ww = w + s - 1;
                    const bool v = vy && ((unsigned)ww < 64u);
                    xv[r * 6 + s] = v ? xc[hh * 64 + ww] : 0.f;
                }
            }
            const float* swc = sw + ci * 324;
#pragma unroll
            for (int o = 0; o < 9; ++o) {
                const float4 wA = *(const float4*)(swc + (18 + o) * 12);
                const float4 wB = *(const float4*)(swc + (18 + o) * 12 + 4);
                const float  w8 = swc[(18 + o) * 12 + 8];
#pragma unroll
                for (int j = 0; j < 4; ++j) {
                    acc[o][j] += wA.x * xv[j]      + wA.y * xv[j + 1]  + wA.z * xv[j + 2]
                               + wA.w * xv[j + 6]  + wB.x * xv[j + 7]  + wB.y * xv[j + 8]
                               + wB.z * xv[j + 12] + wB.w * xv[j + 13] + w8  * xv[j + 14];
                }
            }
        }
#pragma unroll
        for (int o = 0; o < 9; ++o) {
            float4 v; v.x = acc[o][0]; v.y = acc[o][1]; v.z = acc[o][2]; v.w = acc[o][3];
            *(float4*)(outp + (18 + o) * HW + p) = v;
        }
    }
}

// ---------------------------------------------------------------------------
// Kernel 2: sampling v3 (R12) — warp = (pixel,tap), lanes split channels;
// SVROW=37 for conflict-free phase B. Sums G=32 conv partials in phase 0.
// ---------------------------------------------------------------------------
#define SVROW 37
#define SAMPLE_DSMEM (288 * SVROW * 4)   // 42624 B
__global__ __launch_bounds__(256)
void sample_kernel(const float* __restrict__ ob,   // [18]
                   const float* __restrict__ mb)   // [9]
{
    __shared__ int   sl0[288], sl1[288], sl2[288], sl3[288];
    __shared__ float sw0[288], sw1[288], sw2[288], sw3[288];
    extern __shared__ uint32_t sv[];

    const int tid  = threadIdx.x;
    const int lane = tid & 31;
    const int wid  = tid >> 5;
    const int b    = blockIdx.y;
    const int p0   = blockIdx.x * 32;

    const float* pb = g_part + (size_t)b * G * 27 * HW;
    for (int pk = tid; pk < 288; pk += 256) {
        const int px = pk / 9;
        const int k  = pk - px * 9;
        const int p  = p0 + px;
        const int h  = p >> 6;
        const int w  = p & 63;

        float dy   = ob[2 * k];
        float dx   = ob[2 * k + 1];
        float mraw = mb[k];
#pragma unroll 8
        for (int g = 0; g < G; ++g) {
            dy   += pb[(size_t)(g * 27 + 2 * k)     * HW + p];
            dx   += pb[(size_t)(g * 27 + 2 * k + 1) * HW + p];
            mraw += pb[(size_t)(g * 27 + 18 + k)    * HW + p];
        }
        const float m = 2.f / (1.f + expf(-mraw));

        const float py  = dy + (float)(h - 1 + k / 3);
        const float px_ = dx + (float)(w - 1 + k % 3);
        const float y0f = floorf(py), x0f = floorf(px_);
        const float wy1 = py - y0f,  wx1 = px_ - x0f;
        const float wy0 = 1.f - wy1, wx0 = 1.f - wx1;
        const int y0 = (int)y0f, x0 = (int)x0f;
        const int y1 = y0 + 1,   x1 = x0 + 1;

        bool v; int yc, xc;
        v = ((unsigned)y0 < 64u) && ((unsigned)x0 < 64u);
        yc = min(max(y0, 0), 63); xc = min(max(x0, 0), 63);
        sl0[pk] = yc * 64 + xc; sw0[pk] = v ? wy0 * wx0 * m : 0.f;
        v = ((unsigned)y0 < 64u) && ((unsigned)x1 < 64u);
        yc = min(max(y0, 0), 63); xc = min(max(x1, 0), 63);
        sl1[pk] = yc * 64 + xc; sw1[pk] = v ? wy0 * wx1 * m : 0.f;
        v = ((unsigned)y1 < 64u) && ((unsigned)x0 < 64u);
        yc = min(max(y1, 0), 63); xc = min(max(x0, 0), 63);
        sl2[pk] = yc * 64 + xc; sw2[pk] = v ? wy1 * wx0 * m : 0.f;
        v = ((unsigned)y1 < 64u) && ((unsigned)x1 < 64u);
        yc = min(max(y1, 0), 63); xc = min(max(x1, 0), 63);
        sl3[pk] = yc * 64 + xc; sw3[pk] = v ? wy1 * wx1 * m : 0.f;
    }
    __syncthreads();

    const __half* xtb = g_xt + (size_t)b * HW * C;
    const int grp = lane >> 3;
    const int lg  = lane & 7;

    for (int c0 = 0; c0 < C; c0 += 64) {
#pragma unroll
        for (int i = 0; i < 9; ++i) {
            const int pk = wid * 36 + i * 4 + grp;
            const int c  = c0 + lg * 8;
            const float w0 = sw0[pk], w1 = sw1[pk], w2 = sw2[pk], w3 = sw3[pk];
            const uint4 v0 = *(const uint4*)(xtb + (size_t)sl0[pk] * C + c);
            const uint4 v1 = *(const uint4*)(xtb + (size_t)sl1[pk] * C + c);
            const uint4 v2 = *(const uint4*)(xtb + (size_t)sl2[pk] * C + c);
            const uint4 v3 = *(const uint4*)(xtb + (size_t)sl3[pk] * C + c);
            float a[8], bb[8], cc[8], dd[8];
            h8f(v0, a); h8f(v1, bb); h8f(v2, cc); h8f(v3, dd);
            uint32_t o[4];
            __half2* oh = (__half2*)o;
#pragma unroll
            for (int j = 0; j < 4; ++j) {
                const float f0 = w0 * a[2*j]   + w1 * bb[2*j]   + w2 * cc[2*j]   + w3 * dd[2*j];
                const float f1 = w0 * a[2*j+1] + w1 * bb[2*j+1] + w2 * cc[2*j+1] + w3 * dd[2*j+1];
                oh[j] = __floats2half2_rn(f0, f1);
            }
            uint32_t* srow = sv + pk * SVROW + lg * 4;
            srow[0] = o[0]; srow[1] = o[1]; srow[2] = o[2]; srow[3] = o[3];
        }
        __syncthreads();

        const __half* svh = (const __half*)sv;
        for (int t = 0; t < 72; ++t) {
            const int r  = wid * 72 + t;
            const int k  = r >> 6;
            const int cl = r & 63;
            const __half val = svh[(size_t)(lane * 9 + k) * (SVROW * 2) + cl];
            g_vh[((size_t)b * CK + (size_t)(c0 + cl) * 9 + k) * HW + p0 + lane] = val;
        }
        __syncthreads();
    }
}

// ---------------------------------------------------------------------------
// Kernel 3: fp16 mma.sync GEMM, split-K by 2 (R12 version, unchanged).
// ---------------------------------------------------------------------------
#define BKH    64
#define ATILEB 16384
#define BTILEB 16384
#define STAGEB (ATILEB + BTILEB)
#define NSTAGE 3
#define NCHH   18
#define GEMM_SMEM (NSTAGE * STAGEB)      // 98304 B

__global__ __launch_bounds__(256, 2)
void gemm_mma_kernel(float* __restrict__ out)
{
    extern __shared__ char smc[];
    const uint32_t sb = smem_u32(smc);

    const int tid  = threadIdx.x;
    const int lane = tid & 31;
    const int wid  = tid >> 5;
    const int bz   = blockIdx.z;
    const int b    = bz >> 1;
    const int kh   = bz & 1;
    const int m0   = blockIdx.y * 128;
    const int n0   = blockIdx.x * 128;

    const __half* gA = g_wh + (size_t)m0 * CK + (size_t)kh * NCHH * BKH;
    const __half* gB = g_vh + (size_t)b * CK * HW + (size_t)kh * NCHH * BKH * HW + n0;

    const int ar  = tid >> 1;
    const int seg = tid & 1;
    const __half* pa = gA + (size_t)ar * CK + seg * 32;
    uint32_t aswo[4];
#pragma unroll
    for (int j = 0; j < 4; ++j)
        aswo[j] = SWZ128((uint32_t)(ar * 128 + seg * 64 + j * 16));

    const int br = tid >> 2;
    const int cg = tid & 3;
    const __half* pv = gB + (size_t)br * HW + cg * 32;
    uint32_t bswo[4];
#pragma unroll
    for (int j = 0; j < 4; ++j) {
        const int cc = cg * 4 + j;
        bswo[j] = ATILEB + (uint32_t)br * 256 + ((uint32_t)(cc ^ (br & 7)) << 4);
    }

#define LOAD_TILE(stage, ch) do {                                             \
        const uint32_t _s = sb + (stage) * STAGEB;                            \
        const __half* _pa = pa + (size_t)(ch) * BKH;                          \
        cp_async16(_s + aswo[0], _pa);                                        \
        cp_async16(_s + aswo[1], _pa + 8);                                    \
        cp_async16(_s + aswo[2], _pa + 16);                                   \
        cp_async16(_s + aswo[3], _pa + 24);                                   \
        const __half* _pv = pv + (size_t)(ch) * BKH * HW;                     \
        cp_async16(_s + bswo[0], _pv);                                        \
        cp_async16(_s + bswo[1], _pv + 8);                                    \
        cp_async16(_s + bswo[2], _pv + 16);                                   \
        cp_async16(_s + bswo[3], _pv + 24);                                   \
    } while (0)

    const int wm = (wid >> 2) * 64;
    const int wn = (wid & 3) * 32;
    uint32_t aOff[4];
#pragma unroll
    for (int mt = 0; mt < 4; ++mt) {
        const uint32_t off = (uint32_t)((wm + mt * 16 + (lane & 15)) * 128
                                        + ((lane & 16) ? 16 : 0));
        aOff[mt] = SWZ128(off);
    }
    const int mIdx = lane >> 3;
    const int koff = ((mIdx & 1) << 3) + (lane & 7);
    const int cc0  = (wn >> 3) + (mIdx >> 1);
    const int cc1  = cc0 + 2;
    const uint32_t bO0 = ATILEB + (uint32_t)koff * 256 + ((uint32_t)(cc0 ^ (koff & 7)) << 4);
    const uint32_t bO1 = ATILEB + (uint32_t)koff * 256 + ((uint32_t)(cc1 ^ (koff & 7)) << 4);

    float c[16][4];
#pragma unroll
    for (int i = 0; i < 16; ++i)
#pragma unroll
        for (int j = 0; j < 4; ++j) c[i][j] = 0.f;

    LOAD_TILE(0, 0); CP_COMMIT();
    LOAD_TILE(1, 1); CP_COMMIT();

    int stage = 0;
    for (int ch = 0; ch < NCHH; ++ch) {
        if (ch + 2 < NCHH) {
            const int ns = (stage + 2 >= NSTAGE) ? stage + 2 - NSTAGE : stage + 2;
            LOAD_TILE(ns, ch + 2);
        }
        CP_COMMIT();
        CP_WAIT(2);
        __syncthreads();

        const uint32_t sbase = sb + stage * STAGEB;
#pragma unroll
        for (int s = 0; s < 4; ++s) {
            uint32_t a[4][4], b0[4], b1[4];
#pragma unroll
            for (int mt = 0; mt < 4; ++mt)
                LDSM4(a[mt], sbase + (aOff[mt] ^ (s << 5)));
            LDSM4T(b0, sbase + bO0 + s * 4096);
            LDSM4T(b1, sbase + bO1 + s * 4096);
#pragma unroll
            for (int mt = 0; mt < 4; ++mt) {
                mma16816(c[mt * 4 + 0], a[mt], &b0[0]);
                mma16816(c[mt * 4 + 1], a[mt], &b0[2]);
                mma16816(c[mt * 4 + 2], a[mt], &b1[0]);
                mma16816(c[mt * 4 + 3], a[mt], &b1[2]);
            }
        }
        __syncthreads();
        stage = (stage + 1 >= NSTAGE) ? 0 : stage + 1;
    }

    float* dstb = (kh == 0) ? out : g_po;
    const int qr = lane >> 2;
    const int qc = lane & 3;
#pragma unroll
    for (int mt = 0; mt < 4; ++mt) {
#pragma unroll
        for (int nt = 0; nt < 4; ++nt) {
            const int o = m0 + wm + mt * 16 + qr;
            const int p = n0 + wn + nt * 8 + 2 * qc;
            float* o0 = dstb + ((size_t)(b * CO + o)) * HW + p;
            float2 v0; v0.x = c[mt * 4 + nt][0]; v0.y = c[mt * 4 + nt][1];
            *(float2*)o0 = v0;
            float2 v1; v1.x = c[mt * 4 + nt][2]; v1.y = c[mt * 4 + nt][3];
            *(float2*)(o0 + 8 * HW) = v1;
        }
    }
}

// ---------------------------------------------------------------------------
// Kernel 4: split-K reduce  out += g_po   (float4; R12 version)
// ---------------------------------------------------------------------------
__global__ __launch_bounds__(256)
void reduce_kernel(float* __restrict__ out)
{
    const int i = blockIdx.x * 256 + threadIdx.x;
    float4 a = ((float4*)out)[i];
    const float4 p = ((const float4*)g_po)[i];
    a.x += p.x; a.y += p.y; a.z += p.z; a.w += p.w;
    ((float4*)out)[i] = a;
}

// ---------------------------------------------------------------------------
extern "C" void kernel_launch(void* const* d_in, const int* in_sizes, int n_in,
                              void* d_out, int out_size)
{
    const float* x   = (const float*)d_in[0];
    const float* res = (const float*)d_in[1];
    const float* ow  = (const float*)d_in[2];
    const float* ob  = (const float*)d_in[3];
    const float* mw  = (const float*)d_in[4];
    const float* mb  = (const float*)d_in[5];
    const float* rw  = (const float*)d_in[6];
    float* out = (float*)d_out;

    static int smem_set = 0;
    if (!smem_set) {
        cudaFuncSetAttribute(gemm_mma_kernel,
                             cudaFuncAttributeMaxDynamicSharedMemorySize, GEMM_SMEM);
        cudaFuncSetAttribute(sample_kernel,
                             cudaFuncAttributeMaxDynamicSharedMemorySize, SAMPLE_DSMEM);
        smem_set = 1;
    }

    conv_offmod_kernel<<<1680, 128>>>(x, res, ow, mw, rw);
    sample_kernel<<<dim3(HW / 32, BATCH), 256, SAMPLE_DSMEM>>>(ob, mb);
    gemm_mma_kernel<<<dim3(HW / 128, CO / 128, BATCH * 2), 256, GEMM_SMEM>>>(out);
    reduce_kernel<<<BATCH * CO * HW / 4 / 256, 256>>>(out);
}